// round 13
// baseline (speedup 1.0000x reference)
#include <cuda_runtime.h>
#include <cstdint>

#define N_TOK 32768
#define DDIM 256
#define KSTAGES 8
#define CDSZ 1024

#define TM 32
#define TN 256
#define NCHUNK 4
#define KQP 32                       // 32 u64 = 64 int32 = 256 int8 k
#define NBLK (N_TOK / TM)            // 1024 main CTAs
#define NBLK_U (N_TOK / 64)          // 512 update CTAs
#define QA_STRIDE 33
#define SMEM_BYTES (KQP * QA_STRIDE * 8 + 8192 * 8)   // 8448 + 65536 = 73984

typedef unsigned long long u64;

// ------------------------- device scratch (no allocs) -------------------------
__device__ float g_res[N_TOK * DDIM];
__device__ float g_cbT[KSTAGES * DDIM * CDSZ];      // d-major fp32 (fallback)
__device__ float g_cnorm[KSTAGES * CDSZ];
__device__ float g_rnorm[N_TOK];
__device__ float g_sc[KSTAGES * CDSZ];              // per-code int8 scale
__device__ u64   g_qb[KSTAGES * NCHUNK * 8192];     // packed int8 codebooks
__device__ float g_scmax[KSTAGES];
__device__ int   g_cqmax[KSTAGES];
__device__ float g_partials[KSTAGES * NBLK_U];
__device__ int   g_enc[N_TOK];
__device__ int   g_list[N_TOK];
__device__ int   g_acount[KSTAGES];

// ------------------------- helpers -------------------------
__device__ __forceinline__ u64 pack2(float x, float y) {
    u64 r; asm("mov.b64 %0, {%1, %2};" : "=l"(r) : "f"(x), "f"(y)); return r;
}
__device__ __forceinline__ float2 unpack2(u64 v) {
    float2 f; asm("mov.b64 {%0, %1}, %2;" : "=f"(f.x), "=f"(f.y) : "l"(v)); return f;
}
__device__ __forceinline__ u64 fma2(u64 a, u64 b, u64 c) {
    u64 d; asm("fma.rn.f32x2 %0, %1, %2, %3;" : "=l"(d) : "l"(a), "l"(b), "l"(c)); return d;
}
__device__ __forceinline__ int dp4a(int a, int b, int c) {
    int d; asm("dp4a.s32.s32 %0, %1, %2, %3;" : "=r"(d) : "r"(a), "r"(b), "r"(c)); return d;
}
__device__ __forceinline__ uint32_t lo32(u64 v) { return (uint32_t)v; }
__device__ __forceinline__ uint32_t hi32(u64 v) { return (uint32_t)(v >> 32); }

// ------------------------- prep: init, transpose, cnorm, quantize cb ------------
__global__ void init_kernel() {
    if (threadIdx.x < KSTAGES) g_acount[threadIdx.x] = 0;
}

__global__ void transpose_cb_kernel(const float* __restrict__ cb) {
    __shared__ float tile[32][33];
    int s = blockIdx.z;
    int d0 = blockIdx.x * 32, c0 = blockIdx.y * 32;
    int tx = threadIdx.x, ty = threadIdx.y;
    const float* src = cb + (size_t)s * CDSZ * DDIM;
    float* dst = g_cbT + (size_t)s * DDIM * CDSZ;
#pragma unroll
    for (int i = 0; i < 32; i += 8)
        tile[ty + i][tx] = src[(size_t)(c0 + ty + i) * DDIM + d0 + tx];
    __syncthreads();
#pragma unroll
    for (int i = 0; i < 32; i += 8)
        dst[(size_t)(d0 + ty + i) * CDSZ + c0 + tx] = tile[tx][ty + i];
}

__global__ void cnorm_kernel(const float* __restrict__ cb) {
    int row = blockIdx.x * 8 + (threadIdx.x >> 5);
    int lane = threadIdx.x & 31;
    const float* p = cb + (size_t)row * DDIM;
    float s = 0.f;
#pragma unroll
    for (int j = 0; j < 8; j++) { float v = p[lane + 32 * j]; s = fmaf(v, v, s); }
#pragma unroll
    for (int off = 16; off; off >>= 1) s += __shfl_xor_sync(0xffffffffu, s, off);
    if (lane == 0) g_cnorm[row] = s;
}

__global__ void prep_qb_kernel(const float* __restrict__ cb) {
    int row = blockIdx.x * 8 + (threadIdx.x >> 5);   // 0..8191 (stage*1024 + c)
    int lane = threadIdx.x & 31;
    int stage = row >> 10, c = row & 1023;
    const float* p = cb + (size_t)row * DDIM;
    float4 p0 = *(const float4*)&p[lane * 8];
    float4 p1 = *(const float4*)&p[lane * 8 + 4];
    float v[8] = {p0.x, p0.y, p0.z, p0.w, p1.x, p1.y, p1.z, p1.w};
    float m = 0.f;
#pragma unroll
    for (int b = 0; b < 8; b++) m = fmaxf(m, fabsf(v[b]));
#pragma unroll
    for (int off = 16; off; off >>= 1) m = fmaxf(m, __shfl_xor_sync(0xffffffffu, m, off));
    float mm = fmaxf(m, 1e-30f);
    float inv = 127.f / mm;
    int q[8], cq = 0;
#pragma unroll
    for (int b = 0; b < 8; b++) { q[b] = __float2int_rn(v[b] * inv); cq += q[b] * q[b]; }
#pragma unroll
    for (int off = 16; off; off >>= 1) cq += __shfl_xor_sync(0xffffffffu, cq, off);
    uint32_t lo = (q[0] & 0xFF) | ((q[1] & 0xFF) << 8) | ((q[2] & 0xFF) << 16) | ((q[3] & 0xFF) << 24);
    uint32_t hi = (q[4] & 0xFF) | ((q[5] & 0xFF) << 8) | ((q[6] & 0xFF) << 16) | ((q[7] & 0xFF) << 24);
    int chunk = c >> 8, cl = c & 255, txc = cl >> 3, jc = cl & 7;
    g_qb[(size_t)(((stage * NCHUNK + chunk) * KQP + lane) * 8 + jc) * 32 + txc] =
        (u64)lo | ((u64)hi << 32);
    if (lane == 0) {
        g_sc[row] = mm / 127.f;
        atomicMax((int*)&g_scmax[stage], __float_as_int(mm / 127.f));
        atomicMax(&g_cqmax[stage], cq);
    }
}

// ------------------------- main: int8 GEMM + approx argmin + exact rescue ---------
extern __shared__ u64 dsm_u64[];

__global__ __launch_bounds__(128, 3) void rvq_main_kernel(
    const float* __restrict__ x,
    const float* __restrict__ cball,
    int stage)
{
    u64* qa = dsm_u64;                       // [KQP][33]
    u64* Bs = dsm_u64 + KQP * QA_STRIDE;     // [KQP][8][32]
    __shared__ float rnorm_s[TM], sr_s[TM], margin_s[TM];
    __shared__ float t3v_s[4][8][3];
    __shared__ int t3i_s[4][8][3];
    __shared__ unsigned ovf_s[4];
    __shared__ float exv_s[4][8][3];

    const int tid = threadIdx.x;
    const int tx = tid & 31, ty = tid >> 5;
    const int tok0 = blockIdx.x * TM;
    const float* src = (stage == 0) ? x : g_res;
    const float* cb = cball + (size_t)stage * CDSZ * DDIM;
    const float scmax = g_scmax[stage];
    const float cqmaxf = (float)g_cqmax[stage];

    // ---- phase A: per-token maxabs, quantize, rnorm (bit-exact chain), margin ----
#pragma unroll
    for (int i = 0; i < 8; i++) {
        int tg = tok0 + ty * 8 + i;
        const float* p = src + (size_t)tg * DDIM;
        float4 p0 = __ldg((const float4*)&p[tx * 8]);
        float4 p1 = __ldg((const float4*)&p[tx * 8 + 4]);
        float v[8] = {p0.x, p0.y, p0.z, p0.w, p1.x, p1.y, p1.z, p1.w};
        float m = 0.f;
#pragma unroll
        for (int b = 0; b < 8; b++) m = fmaxf(m, fabsf(v[b]));
#pragma unroll
        for (int off = 16; off; off >>= 1) m = fmaxf(m, __shfl_xor_sync(0xffffffffu, m, off));
        // rnorm with the reference-matched chain (lane+32j order)
        float s = 0.f;
#pragma unroll
        for (int j = 0; j < 8; j++) { float w = __ldg(&p[tx + 32 * j]); s = fmaf(w, w, s); }
#pragma unroll
        for (int off = 16; off; off >>= 1) s += __shfl_xor_sync(0xffffffffu, s, off);
        float mm = fmaxf(m, 1e-30f);
        float inv = 127.f / mm;
        int q[8];
#pragma unroll
        for (int b = 0; b < 8; b++) q[b] = __float2int_rn(v[b] * inv);
        uint32_t lo = (q[0] & 0xFF) | ((q[1] & 0xFF) << 8) | ((q[2] & 0xFF) << 16) | ((q[3] & 0xFF) << 24);
        uint32_t hi = (q[4] & 0xFF) | ((q[5] & 0xFF) << 8) | ((q[6] & 0xFF) << 16) | ((q[7] & 0xFF) << 24);
        qa[tx * QA_STRIDE + ty * 8 + i] = (u64)lo | ((u64)hi << 32);
        if (tx == 0) {
            int t = ty * 8 + i;
            float srt = mm / 127.f;
            rnorm_s[t] = s;
            sr_s[t] = srt;
            margin_s[t] = 40.f * scmax * sqrtf((s + srt * srt * scmax * scmax * cqmaxf) / 12.f);
            g_rnorm[tg] = s;
        }
    }
    if (tid < 4) ovf_s[tid] = 0;

    // per-token top-3 approx trackers
    float v0[8], v1[8], v2[8];
    int i0[8], i1a[8], i2a[8];
    unsigned ovfm = 0;
#pragma unroll
    for (int i = 0; i < 8; i++) { v0[i] = v1[i] = v2[i] = 3.4e38f; i0[i] = i1a[i] = i2a[i] = 0; }

    for (int chunk = 0; chunk < NCHUNK; chunk++) {
        __syncthreads();  // phase A (chunk0) / prior epilogue done with Bs
        const u64* gb = g_qb + (size_t)(stage * NCHUNK + chunk) * 8192;
#pragma unroll
        for (int r = 0; r < 64; r++) Bs[r * 128 + tid] = __ldg(&gb[r * 128 + tid]);
        __syncthreads();

        float sc8[8], cn8[8];
#pragma unroll
        for (int j = 0; j < 8; j++) {
            int c = stage * CDSZ + chunk * 256 + tx * 8 + j;
            sc8[j] = __ldg(&g_sc[c]);
            cn8[j] = __ldg(&g_cnorm[c]);
        }
        int acc[8][8];
#pragma unroll
        for (int i = 0; i < 8; i++)
#pragma unroll
            for (int j = 0; j < 8; j++) acc[i][j] = 0;

#pragma unroll 4
        for (int kqp = 0; kqp < KQP; kqp++) {
            u64 a8[8], b8[8];
#pragma unroll
            for (int i = 0; i < 8; i++) a8[i] = qa[kqp * QA_STRIDE + ty * 8 + i];
#pragma unroll
            for (int j = 0; j < 8; j++) b8[j] = Bs[kqp * 256 + j * 32 + tx];
#pragma unroll
            for (int i = 0; i < 8; i++)
#pragma unroll
                for (int j = 0; j < 8; j++) {
                    acc[i][j] = dp4a(lo32(a8[i]), lo32(b8[j]), acc[i][j]);
                    acc[i][j] = dp4a(hi32(a8[i]), hi32(b8[j]), acc[i][j]);
                }
        }

        // epilogue: approx d2 + top-3 insert with eviction-overflow
#pragma unroll
        for (int i = 0; i < 8; i++) {
            float R = rnorm_s[ty * 8 + i];
            float M = margin_s[ty * 8 + i];
            float srt = sr_s[ty * 8 + i];
#pragma unroll
            for (int j = 0; j < 8; j++) {
                float ad2 = fmaf(-2.f * srt * sc8[j], (float)acc[i][j], R) + cn8[j];
                int idx = chunk * 256 + tx * 8 + j;
                float ev;
                if (ad2 < v2[i]) {
                    ev = v2[i];
                    if (ad2 < v1[i]) {
                        v2[i] = v1[i]; i2a[i] = i1a[i];
                        if (ad2 < v0[i]) { v1[i] = v0[i]; i1a[i] = i0[i]; v0[i] = ad2; i0[i] = idx; }
                        else { v1[i] = ad2; i1a[i] = idx; }
                    } else { v2[i] = ad2; i2a[i] = idx; }
                } else ev = ad2;
                if (ev <= v0[i] + M) ovfm |= (1u << i);
            }
        }
    }

    // cross-lane top-3 merge (butterfly over 32 lanes)
#pragma unroll
    for (int off = 1; off <= 16; off <<= 1) {
        unsigned oovf = __shfl_xor_sync(0xffffffffu, ovfm, off);
        ovfm |= oovf;
#pragma unroll
        for (int i = 0; i < 8; i++) {
            float M = margin_s[ty * 8 + i];
            float ov[3]; int oi[3];
            ov[0] = __shfl_xor_sync(0xffffffffu, v0[i], off);
            oi[0] = __shfl_xor_sync(0xffffffffu, i0[i], off);
            ov[1] = __shfl_xor_sync(0xffffffffu, v1[i], off);
            oi[1] = __shfl_xor_sync(0xffffffffu, i1a[i], off);
            ov[2] = __shfl_xor_sync(0xffffffffu, v2[i], off);
            oi[2] = __shfl_xor_sync(0xffffffffu, i2a[i], off);
#pragma unroll
            for (int s2 = 0; s2 < 3; s2++) {
                float nv = ov[s2]; int ni = oi[s2];
                float evv;
                if (nv < v2[i]) {
                    evv = v2[i];
                    if (nv < v1[i]) {
                        v2[i] = v1[i]; i2a[i] = i1a[i];
                        if (nv < v0[i]) { v1[i] = v0[i]; i1a[i] = i0[i]; v0[i] = nv; i0[i] = ni; }
                        else { v1[i] = nv; i1a[i] = ni; }
                    } else { v2[i] = nv; i2a[i] = ni; }
                } else evv = nv;
                if (evv <= v0[i] + M) ovfm |= (1u << i);
            }
        }
    }

    // publish merged results to smem (lane 0 per warp)
    if (tx == 0) {
#pragma unroll
        for (int i = 0; i < 8; i++) {
            t3v_s[ty][i][0] = v0[i]; t3i_s[ty][i][0] = i0[i];
            t3v_s[ty][i][1] = v1[i]; t3i_s[ty][i][1] = i1a[i];
            t3v_s[ty][i][2] = v2[i]; t3i_s[ty][i][2] = i2a[i];
        }
        ovf_s[ty] = ovfm;
    }
    __syncwarp();

    // exact rescue: lanes 0..23, lane = i*3 + slot
    if (tx < 24) {
        int i = tx / 3, slot = tx - i * 3;
        float M = margin_s[ty * 8 + i];
        float b0 = t3v_s[ty][i][0];
        bool tokov = (ovf_s[ty] >> i) & 1;
        int nc = 1 + (t3v_s[ty][i][1] <= b0 + M ? 1 : 0) + (t3v_s[ty][i][2] <= b0 + M ? 1 : 0);
        bool valid = !tokov && nc > 1 && (slot == 0 || t3v_s[ty][i][slot] <= b0 + M);
        float ex = 3.4e38f;
        if (valid) {
            int cand = t3i_s[ty][i][slot];
            int tg = tok0 + ty * 8 + i;
            const float* rp = src + (size_t)tg * DDIM;
            const float* cp = cb + (size_t)cand * DDIM;
            float dot = 0.f;
#pragma unroll 8
            for (int k = 0; k < DDIM; k++) dot = fmaf(__ldg(&rp[k]), __ldg(&cp[k]), dot);
            ex = __fadd_rn(__fsub_rn(rnorm_s[ty * 8 + i], __fmul_rn(2.0f, dot)),
                           __ldg(&g_cnorm[stage * CDSZ + cand]));
        }
        exv_s[ty][i][slot] = ex;
    }
    __syncwarp();

    // final selection: lanes 0..7 = token i
    if (tx < 8) {
        int i = tx;
        int tg = tok0 + ty * 8 + i;
        float M = margin_s[ty * 8 + i];
        bool tokov = (ovf_s[ty] >> i) & 1;
        if (tokov) {
            int p = atomicAdd(&g_acount[stage], 1);
            g_list[p] = tg;
        } else {
            float b0 = t3v_s[ty][i][0];
            int nc = 1 + (t3v_s[ty][i][1] <= b0 + M ? 1 : 0) + (t3v_s[ty][i][2] <= b0 + M ? 1 : 0);
            int enc;
            if (nc == 1) enc = t3i_s[ty][i][0];
            else {
                float bv = 3.4e38f; int bi = 0x7fffffff;
#pragma unroll
                for (int s2 = 0; s2 < 3; s2++) {
                    bool v = (s2 == 0) || (t3v_s[ty][i][s2] <= b0 + M);
                    if (!v) continue;
                    float ev = exv_s[ty][i][s2];
                    int ei = t3i_s[ty][i][s2];
                    if (ev < bv || (ev == bv && ei < bi)) { bv = ev; bi = ei; }
                }
                enc = bi;
            }
            g_enc[tg] = enc;
        }
    }
}

// ------------------------- exact full-scan fallback (R4-proven chain) --------------
__global__ __launch_bounds__(256) void fallback_kernel(const float* __restrict__ x, int stage) {
    const float* src = (stage == 0) ? x : g_res;
    const float* cbT = g_cbT + (size_t)stage * DDIM * CDSZ;
    const float* cn = g_cnorm + stage * CDSZ;
    int lane = threadIdx.x & 31;
    int gw = (blockIdx.x * blockDim.x + threadIdx.x) >> 5;
    int nw = (gridDim.x * blockDim.x) >> 5;
    int count = g_acount[stage];
    for (int li = gw; li < count; li += nw) {
        int t = g_list[li];
        const float* r = src + (size_t)t * DDIM;
        float R = g_rnorm[t];
        float bv = 3.4e38f; int bi = 0;
        for (int jb = 0; jb < 4; jb++) {
            u64 acc[4] = {0ull, 0ull, 0ull, 0ull};
            int cbase = lane + 256 * jb;
            for (int k = 0; k < DDIM; k++) {
                float rv = __ldg(&r[k]);
                u64 rp = pack2(rv, rv);
                const float* row = cbT + (size_t)k * CDSZ;
#pragma unroll
                for (int p = 0; p < 4; p++) {
                    int c1 = cbase + 64 * p;
                    acc[p] = fma2(rp, pack2(__ldg(&row[c1]), __ldg(&row[c1 + 32])), acc[p]);
                }
            }
#pragma unroll
            for (int p = 0; p < 4; p++) {
                float2 f = unpack2(acc[p]);
                int c1 = cbase + 64 * p;
                float d2x = __fadd_rn(__fsub_rn(R, __fmul_rn(2.0f, f.x)), __ldg(&cn[c1]));
                float d2y = __fadd_rn(__fsub_rn(R, __fmul_rn(2.0f, f.y)), __ldg(&cn[c1 + 32]));
                if (d2x < bv) { bv = d2x; bi = c1; }
                if (d2y < bv) { bv = d2y; bi = c1 + 32; }
            }
        }
#pragma unroll
        for (int off = 16; off; off >>= 1) {
            float ov = __shfl_xor_sync(0xffffffffu, bv, off);
            int oi = __shfl_xor_sync(0xffffffffu, bi, off);
            if (ov < bv || (ov == bv && oi < bi)) { bv = ov; bi = oi; }
        }
        if (lane == 0) g_enc[t] = bi;
    }
}

// ------------------------- update (R7-proven) + stage-7 quant --------------------
__global__ __launch_bounds__(128) void update_kernel(const float* __restrict__ x,
                                                     const float* __restrict__ cb,
                                                     int stage, float* __restrict__ out) {
    __shared__ float wsum[4];
    float* encf = out + 2;
    float* quant = out + 2 + (size_t)N_TOK * KSTAGES;
    const float* src = (stage == 0) ? x : g_res;
    const int tid = threadIdx.x;
    const int warpId = tid >> 5, lane = tid & 31;
    const int tok0 = blockIdx.x * 64;
    float lsum = 0.f;
    for (int t = warpId; t < 64; t += 4) {
        int token = tok0 + t;
        int e = g_enc[token];
        const float* crow = cb + (size_t)e * DDIM;
#pragma unroll
        for (int jj = 0; jj < 8; jj++) {
            int d = lane + jj * 32;
            float r = __ldg(&src[(size_t)token * DDIM + d]);
            float c = __ldg(&crow[d]);
            float nr = r - c;
            g_res[(size_t)token * DDIM + d] = nr;
            if (stage == KSTAGES - 1)
                quant[(size_t)token * DDIM + d] = __ldg(&x[(size_t)token * DDIM + d]) - nr;
            lsum = fmaf(nr, nr, lsum);
        }
        if (lane == 0) encf[(size_t)token * KSTAGES + stage] = (float)e;
    }
#pragma unroll
    for (int off = 16; off; off >>= 1) lsum += __shfl_xor_sync(0xffffffffu, lsum, off);
    if (lane == 0) wsum[warpId] = lsum;
    __syncthreads();
    if (tid == 0)
        g_partials[stage * NBLK_U + blockIdx.x] = wsum[0] + wsum[1] + wsum[2] + wsum[3];
}

// ------------------------- epilogue -------------------------
__global__ void finalize_kernel(float* __restrict__ out) {
    __shared__ float sh[256];
    int tid = threadIdx.x;
    float s = 0.f;
    for (int i = tid; i < KSTAGES * NBLK_U; i += 256) s += g_partials[i];
    sh[tid] = s;
    __syncthreads();
    for (int off = 128; off; off >>= 1) {
        if (tid < off) sh[tid] += sh[tid + off];
        __syncthreads();
    }
    if (tid == 0) {
        float loss = sh[0] * (1.0f / (float)((size_t)N_TOK * DDIM));
        out[0] = loss;
        out[1] = loss;
    }
}

// ------------------------- launch -------------------------
extern "C" void kernel_launch(void* const* d_in, const int* in_sizes, int n_in,
                              void* d_out, int out_size) {
    const float* x  = (const float*)d_in[0];
    const float* cb = (const float*)d_in[1];
    if (n_in >= 2 && in_sizes[0] == KSTAGES * CDSZ * DDIM && in_sizes[1] == N_TOK * DDIM) {
        const float* t = x; x = cb; cb = t;
    }
    float* out = (float*)d_out;

    cudaFuncSetAttribute(rvq_main_kernel,
                         cudaFuncAttributeMaxDynamicSharedMemorySize, SMEM_BYTES);

    init_kernel<<<1, 32>>>();
    transpose_cb_kernel<<<dim3(8, 32, 8), dim3(32, 8)>>>(cb);
    cnorm_kernel<<<(KSTAGES * CDSZ) / 8, 256>>>(cb);
    prep_qb_kernel<<<(KSTAGES * CDSZ) / 8, 256>>>(cb);

    for (int s = 0; s < KSTAGES; s++) {
        rvq_main_kernel<<<NBLK, 128, SMEM_BYTES>>>(x, cb, s);
        fallback_kernel<<<128, 256>>>(x, s);
        // FIX (R12 root cause): update must use THIS STAGE's codebook
        update_kernel<<<NBLK_U, 128>>>(x, cb + (size_t)s * CDSZ * DDIM, s, out);
    }

    finalize_kernel<<<1, 256>>>(out);
}

// round 14
// speedup vs baseline: 61.6290x; 61.6290x over previous
#include <cuda_runtime.h>
#include <cstdint>

#define N_TOK 32768
#define DDIM 256
#define KSTAGES 8
#define CDSZ 1024

#define TM 32
#define NCHUNK 4
#define KQP 32                       // 32 u64 = 256 int8 k
#define NBLK (N_TOK / TM)            // 1024 main CTAs
#define NBLK_U (N_TOK / 64)          // 512 update CTAs
#define QA_STRIDE 33
#define QCAP 4096
#define SMEM_BYTES (KQP * QA_STRIDE * 8 + 8192 * 8)   // 73984 (dynamic: qa + Bs)

typedef unsigned long long u64;

// ------------------------- device scratch (no allocs) -------------------------
__device__ float g_res[N_TOK * DDIM];
__device__ float g_cbT[KSTAGES * DDIM * CDSZ];      // d-major fp32 (fallback)
__device__ float g_cnorm[KSTAGES * CDSZ];
__device__ float g_rnorm[N_TOK];
__device__ float g_sc[KSTAGES * CDSZ];
__device__ u64   g_qb[KSTAGES * NCHUNK * 8192];
__device__ float g_scmax[KSTAGES];
__device__ float g_cnmax[KSTAGES];
__device__ float g_partials[KSTAGES * NBLK_U];
__device__ int   g_enc[N_TOK];
__device__ int   g_list[N_TOK];
__device__ int   g_acount[KSTAGES];

// ------------------------- helpers -------------------------
__device__ __forceinline__ u64 pack2(float x, float y) {
    u64 r; asm("mov.b64 %0, {%1, %2};" : "=l"(r) : "f"(x), "f"(y)); return r;
}
__device__ __forceinline__ float2 unpack2(u64 v) {
    float2 f; asm("mov.b64 {%0, %1}, %2;" : "=f"(f.x), "=f"(f.y) : "l"(v)); return f;
}
__device__ __forceinline__ u64 fma2(u64 a, u64 b, u64 c) {
    u64 d; asm("fma.rn.f32x2 %0, %1, %2, %3;" : "=l"(d) : "l"(a), "l"(b), "l"(c)); return d;
}
__device__ __forceinline__ int dp4a(int a, int b, int c) {
    int d; asm("dp4a.s32.s32 %0, %1, %2, %3;" : "=r"(d) : "r"(a), "r"(b), "r"(c)); return d;
}
__device__ __forceinline__ uint32_t lo32(u64 v) { return (uint32_t)v; }
__device__ __forceinline__ uint32_t hi32(u64 v) { return (uint32_t)(v >> 32); }
__device__ __forceinline__ uint32_t fflip(float f) {
    uint32_t u = __float_as_uint(f);
    return (u & 0x80000000u) ? ~u : (u | 0x80000000u);
}

// ------------------------- prep -------------------------
__global__ void init_kernel() {
    if (threadIdx.x < KSTAGES) g_acount[threadIdx.x] = 0;
}

__global__ void transpose_cb_kernel(const float* __restrict__ cb) {
    __shared__ float tile[32][33];
    int s = blockIdx.z;
    int d0 = blockIdx.x * 32, c0 = blockIdx.y * 32;
    int tx = threadIdx.x, ty = threadIdx.y;
    const float* src = cb + (size_t)s * CDSZ * DDIM;
    float* dst = g_cbT + (size_t)s * DDIM * CDSZ;
#pragma unroll
    for (int i = 0; i < 32; i += 8)
        tile[ty + i][tx] = src[(size_t)(c0 + ty + i) * DDIM + d0 + tx];
    __syncthreads();
#pragma unroll
    for (int i = 0; i < 32; i += 8)
        dst[(size_t)(d0 + ty + i) * CDSZ + c0 + tx] = tile[tx][ty + i];
}

__global__ void cnorm_kernel(const float* __restrict__ cb) {
    int row = blockIdx.x * 8 + (threadIdx.x >> 5);
    int lane = threadIdx.x & 31;
    int stage = row >> 10;
    const float* p = cb + (size_t)row * DDIM;
    float s = 0.f;
#pragma unroll
    for (int j = 0; j < 8; j++) { float v = p[lane + 32 * j]; s = fmaf(v, v, s); }
#pragma unroll
    for (int off = 16; off; off >>= 1) s += __shfl_xor_sync(0xffffffffu, s, off);
    if (lane == 0) {
        g_cnorm[row] = s;
        atomicMax((int*)&g_cnmax[stage], __float_as_int(s));
    }
}

__global__ void prep_qb_kernel(const float* __restrict__ cb) {
    int row = blockIdx.x * 8 + (threadIdx.x >> 5);
    int lane = threadIdx.x & 31;
    int stage = row >> 10, c = row & 1023;
    const float* p = cb + (size_t)row * DDIM;
    float4 p0 = *(const float4*)&p[lane * 8];
    float4 p1 = *(const float4*)&p[lane * 8 + 4];
    float v[8] = {p0.x, p0.y, p0.z, p0.w, p1.x, p1.y, p1.z, p1.w};
    float m = 0.f;
#pragma unroll
    for (int b = 0; b < 8; b++) m = fmaxf(m, fabsf(v[b]));
#pragma unroll
    for (int off = 16; off; off >>= 1) m = fmaxf(m, __shfl_xor_sync(0xffffffffu, m, off));
    float mm = fmaxf(m, 1e-30f);
    float inv = 127.f / mm;
    int q[8];
#pragma unroll
    for (int b = 0; b < 8; b++) q[b] = __float2int_rn(v[b] * inv);
    uint32_t lo = (q[0] & 0xFF) | ((q[1] & 0xFF) << 8) | ((q[2] & 0xFF) << 16) | ((q[3] & 0xFF) << 24);
    uint32_t hi = (q[4] & 0xFF) | ((q[5] & 0xFF) << 8) | ((q[6] & 0xFF) << 16) | ((q[7] & 0xFF) << 24);
    int chunk = c >> 8, cl = c & 255, txc = cl >> 3, jc = cl & 7;
    g_qb[(size_t)(((stage * NCHUNK + chunk) * KQP + lane) * 8 + jc) * 32 + txc] =
        (u64)lo | ((u64)hi << 32);
    if (lane == 0) {
        g_sc[row] = mm / 127.f;
        atomicMax((int*)&g_scmax[stage], __float_as_int(mm / 127.f));
    }
}

// ------------------------- main: int8 GEMM + sound candidate queue + exact rescore ----
extern __shared__ u64 dsm_u64[];

__global__ __launch_bounds__(128, 2) void rvq_main_kernel(
    const float* __restrict__ x,
    const float* __restrict__ cball,
    int stage)
{
    u64* qa = dsm_u64;                       // [KQP][33]
    u64* Bs = dsm_u64 + KQP * QA_STRIDE;     // [KQP][8][32]
    __shared__ float rnorm_s[TM], sr_s[TM], margin_s[TM];
    __shared__ u64 best_s[TM];
    __shared__ unsigned short queue_s[QCAP];
    __shared__ int qcount_s;

    const int tid = threadIdx.x;
    const int tx = tid & 31, ty = tid >> 5;
    const int tok0 = blockIdx.x * TM;
    const float* src = (stage == 0) ? x : g_res;
    const float* cb = cball + (size_t)stage * CDSZ * DDIM;
    const float scmax = g_scmax[stage];
    const float cnmax = g_cnmax[stage];

    if (tid == 0) qcount_s = 0;
    if (tid < TM) best_s[tid] = ~0ull;

    // ---- phase A: per-token quantize + rnorm (reference chain) + margin ----
#pragma unroll
    for (int i = 0; i < 8; i++) {
        int tg = tok0 + ty * 8 + i;
        const float* p = src + (size_t)tg * DDIM;
        float4 p0 = __ldg((const float4*)&p[tx * 8]);
        float4 p1 = __ldg((const float4*)&p[tx * 8 + 4]);
        float v[8] = {p0.x, p0.y, p0.z, p0.w, p1.x, p1.y, p1.z, p1.w};
        float m = 0.f;
#pragma unroll
        for (int b = 0; b < 8; b++) m = fmaxf(m, fabsf(v[b]));
#pragma unroll
        for (int off = 16; off; off >>= 1) m = fmaxf(m, __shfl_xor_sync(0xffffffffu, m, off));
        float s = 0.f;
#pragma unroll
        for (int j = 0; j < 8; j++) { float w = __ldg(&p[tx + 32 * j]); s = fmaf(w, w, s); }
#pragma unroll
        for (int off = 16; off; off >>= 1) s += __shfl_xor_sync(0xffffffffu, s, off);
        float mm = fmaxf(m, 1e-30f);
        float inv = 127.f / mm;
        int q[8];
#pragma unroll
        for (int b = 0; b < 8; b++) q[b] = __float2int_rn(v[b] * inv);
        uint32_t lo = (q[0] & 0xFF) | ((q[1] & 0xFF) << 8) | ((q[2] & 0xFF) << 16) | ((q[3] & 0xFF) << 24);
        uint32_t hi = (q[4] & 0xFF) | ((q[5] & 0xFF) << 8) | ((q[6] & 0xFF) << 16) | ((q[7] & 0xFF) << 24);
        qa[tx * QA_STRIDE + ty * 8 + i] = (u64)lo | ((u64)hi << 32);
        if (tx == 0) {
            int t = ty * 8 + i;
            float srt = mm / 127.f;
            rnorm_s[t] = s;
            sr_s[t] = srt;
            // M = 2E, E = 16*sigma_dot ; sigma_dot^2 = (sc^2*R + sr^2*C)/12
            margin_s[t] = 32.f * sqrtf((scmax * scmax * s + srt * srt * cnmax) * (1.f / 12.f));
            g_rnorm[tg] = s;
        }
    }
    __syncthreads();

    float R8[8], M8[8], sr8[8], m_run[8];
#pragma unroll
    for (int i = 0; i < 8; i++) {
        R8[i] = rnorm_s[ty * 8 + i];
        M8[i] = margin_s[ty * 8 + i];
        sr8[i] = sr_s[ty * 8 + i];
        m_run[i] = 3.4e38f;
    }

    for (int chunk = 0; chunk < NCHUNK; chunk++) {
        __syncthreads();
        const u64* gb = g_qb + (size_t)(stage * NCHUNK + chunk) * 8192;
#pragma unroll
        for (int r = 0; r < 64; r++) Bs[r * 128 + tid] = __ldg(&gb[r * 128 + tid]);
        __syncthreads();

        float sc8[8], cn8[8];
#pragma unroll
        for (int j = 0; j < 8; j++) {
            int c = stage * CDSZ + chunk * 256 + tx * 8 + j;
            sc8[j] = __ldg(&g_sc[c]);
            cn8[j] = __ldg(&g_cnorm[c]);
        }
        int acc[8][8];
#pragma unroll
        for (int i = 0; i < 8; i++)
#pragma unroll
            for (int j = 0; j < 8; j++) acc[i][j] = 0;

#pragma unroll 4
        for (int kqp = 0; kqp < KQP; kqp++) {
            u64 a8[8], b8[8];
#pragma unroll
            for (int i = 0; i < 8; i++) a8[i] = qa[kqp * QA_STRIDE + ty * 8 + i];
#pragma unroll
            for (int j = 0; j < 8; j++) b8[j] = Bs[kqp * 256 + j * 32 + tx];
#pragma unroll
            for (int i = 0; i < 8; i++)
#pragma unroll
                for (int j = 0; j < 8; j++) {
                    acc[i][j] = dp4a(lo32(a8[i]), lo32(b8[j]), acc[i][j]);
                    acc[i][j] = dp4a(hi32(a8[i]), hi32(b8[j]), acc[i][j]);
                }
        }

        // step 1: update running approx-min per token (warp-local tokens)
#pragma unroll
        for (int i = 0; i < 8; i++) {
            float tmin = 3.4e38f;
#pragma unroll
            for (int j = 0; j < 8; j++) {
                float ad2 = fmaf(-2.f * sr8[i] * sc8[j], (float)acc[i][j], R8[i]) + cn8[j];
                tmin = fminf(tmin, ad2);
            }
#pragma unroll
            for (int off = 16; off; off >>= 1)
                tmin = fminf(tmin, __shfl_xor_sync(0xffffffffu, tmin, off));
            m_run[i] = fminf(m_run[i], tmin);
        }

        // step 2: queue all candidates with ad2 <= m_run + M  (sound: M = 2E)
#pragma unroll
        for (int i = 0; i < 8; i++) {
            float thr = m_run[i] + M8[i];
#pragma unroll
            for (int j = 0; j < 8; j++) {
                float ad2 = fmaf(-2.f * sr8[i] * sc8[j], (float)acc[i][j], R8[i]) + cn8[j];
                if (ad2 <= thr) {
                    int pos = atomicAdd(&qcount_s, 1);
                    if (pos < QCAP) {
                        int code = chunk * 256 + tx * 8 + j;
                        queue_s[pos] = (unsigned short)(((ty * 8 + i) << 10) | code);
                    }
                }
            }
        }
    }
    __syncthreads();

    const int qn = qcount_s;
    if (qn > QCAP) {
        // overflow (statistically negligible): defer entire CTA to exact fallback
        if (tid < TM) {
            int p = atomicAdd(&g_acount[stage], 1);
            g_list[p] = tok0 + tid;
        }
        return;
    }

    // exact rescore of queued candidates (reference-matched serial chain)
    for (int e = tid; e < qn; e += 128) {
        unsigned short ent = queue_s[e];
        int t = ent >> 10;
        int code = ent & 1023;
        const float* rp = src + (size_t)(tok0 + t) * DDIM;
        const float* cp = cb + (size_t)code * DDIM;
        float dot = 0.f;
#pragma unroll 8
        for (int k = 0; k < DDIM; k++) dot = fmaf(__ldg(&rp[k]), __ldg(&cp[k]), dot);
        float d2 = __fadd_rn(__fsub_rn(rnorm_s[t], __fmul_rn(2.0f, dot)),
                             __ldg(&g_cnorm[stage * CDSZ + code]));
        u64 key = ((u64)fflip(d2) << 32) | (uint32_t)code;
        atomicMin(&best_s[t], key);
    }
    __syncthreads();

    if (tid < TM) g_enc[tok0 + tid] = (int)(uint32_t)best_s[tid];
}

// ------------------------- exact full-scan fallback (proven chain) --------------
__global__ __launch_bounds__(256) void fallback_kernel(const float* __restrict__ x, int stage) {
    const float* src = (stage == 0) ? x : g_res;
    const float* cbT = g_cbT + (size_t)stage * DDIM * CDSZ;
    const float* cn = g_cnorm + stage * CDSZ;
    int lane = threadIdx.x & 31;
    int gw = (blockIdx.x * blockDim.x + threadIdx.x) >> 5;
    int nw = (gridDim.x * blockDim.x) >> 5;
    int count = g_acount[stage];
    for (int li = gw; li < count; li += nw) {
        int t = g_list[li];
        const float* r = src + (size_t)t * DDIM;
        float R = g_rnorm[t];
        float bv = 3.4e38f; int bi = 0;
        for (int jb = 0; jb < 4; jb++) {
            u64 acc[4] = {0ull, 0ull, 0ull, 0ull};
            int cbase = lane + 256 * jb;
            for (int k = 0; k < DDIM; k++) {
                float rv = __ldg(&r[k]);
                u64 rp = pack2(rv, rv);
                const float* row = cbT + (size_t)k * CDSZ;
#pragma unroll
                for (int p = 0; p < 4; p++) {
                    int c1 = cbase + 64 * p;
                    acc[p] = fma2(rp, pack2(__ldg(&row[c1]), __ldg(&row[c1 + 32])), acc[p]);
                }
            }
#pragma unroll
            for (int p = 0; p < 4; p++) {
                float2 f = unpack2(acc[p]);
                int c1 = cbase + 64 * p;
                float d2x = __fadd_rn(__fsub_rn(R, __fmul_rn(2.0f, f.x)), __ldg(&cn[c1]));
                float d2y = __fadd_rn(__fsub_rn(R, __fmul_rn(2.0f, f.y)), __ldg(&cn[c1 + 32]));
                if (d2x < bv) { bv = d2x; bi = c1; }
                if (d2y < bv) { bv = d2y; bi = c1 + 32; }
            }
        }
#pragma unroll
        for (int off = 16; off; off >>= 1) {
            float ov = __shfl_xor_sync(0xffffffffu, bv, off);
            int oi = __shfl_xor_sync(0xffffffffu, bi, off);
            if (ov < bv || (ov == bv && oi < bi)) { bv = ov; bi = oi; }
        }
        if (lane == 0) g_enc[t] = bi;
    }
}

// ------------------------- update + stage-7 quant --------------------
__global__ __launch_bounds__(128) void update_kernel(const float* __restrict__ x,
                                                     const float* __restrict__ cb,
                                                     int stage, float* __restrict__ out) {
    __shared__ float wsum[4];
    float* encf = out + 2;
    float* quant = out + 2 + (size_t)N_TOK * KSTAGES;
    const float* src = (stage == 0) ? x : g_res;
    const int tid = threadIdx.x;
    const int warpId = tid >> 5, lane = tid & 31;
    const int tok0 = blockIdx.x * 64;
    float lsum = 0.f;
    for (int t = warpId; t < 64; t += 4) {
        int token = tok0 + t;
        int e = g_enc[token];
        const float* crow = cb + (size_t)e * DDIM;
#pragma unroll
        for (int jj = 0; jj < 8; jj++) {
            int d = lane + jj * 32;
            float r = __ldg(&src[(size_t)token * DDIM + d]);
            float c = __ldg(&crow[d]);
            float nr = r - c;
            g_res[(size_t)token * DDIM + d] = nr;
            if (stage == KSTAGES - 1)
                quant[(size_t)token * DDIM + d] = __ldg(&x[(size_t)token * DDIM + d]) - nr;
            lsum = fmaf(nr, nr, lsum);
        }
        if (lane == 0) encf[(size_t)token * KSTAGES + stage] = (float)e;
    }
#pragma unroll
    for (int off = 16; off; off >>= 1) lsum += __shfl_xor_sync(0xffffffffu, lsum, off);
    if (lane == 0) wsum[warpId] = lsum;
    __syncthreads();
    if (tid == 0)
        g_partials[stage * NBLK_U + blockIdx.x] = wsum[0] + wsum[1] + wsum[2] + wsum[3];
}

// ------------------------- epilogue -------------------------
__global__ void finalize_kernel(float* __restrict__ out) {
    __shared__ float sh[256];
    int tid = threadIdx.x;
    float s = 0.f;
    for (int i = tid; i < KSTAGES * NBLK_U; i += 256) s += g_partials[i];
    sh[tid] = s;
    __syncthreads();
    for (int off = 128; off; off >>= 1) {
        if (tid < off) sh[tid] += sh[tid + off];
        __syncthreads();
    }
    if (tid == 0) {
        float loss = sh[0] * (1.0f / (float)((size_t)N_TOK * DDIM));
        out[0] = loss;
        out[1] = loss;
    }
}

// ------------------------- launch -------------------------
extern "C" void kernel_launch(void* const* d_in, const int* in_sizes, int n_in,
                              void* d_out, int out_size) {
    const float* x  = (const float*)d_in[0];
    const float* cb = (const float*)d_in[1];
    if (n_in >= 2 && in_sizes[0] == KSTAGES * CDSZ * DDIM && in_sizes[1] == N_TOK * DDIM) {
        const float* t = x; x = cb; cb = t;
    }
    float* out = (float*)d_out;

    cudaFuncSetAttribute(rvq_main_kernel,
                         cudaFuncAttributeMaxDynamicSharedMemorySize, SMEM_BYTES);

    init_kernel<<<1, 32>>>();
    transpose_cb_kernel<<<dim3(8, 32, 8), dim3(32, 8)>>>(cb);
    cnorm_kernel<<<(KSTAGES * CDSZ) / 8, 256>>>(cb);
    prep_qb_kernel<<<(KSTAGES * CDSZ) / 8, 256>>>(cb);

    for (int s = 0; s < KSTAGES; s++) {
        rvq_main_kernel<<<NBLK, 128, SMEM_BYTES>>>(x, cb, s);
        fallback_kernel<<<128, 256>>>(x, s);
        update_kernel<<<NBLK_U, 128>>>(x, cb + (size_t)s * CDSZ * DDIM, s, out);
    }

    finalize_kernel<<<1, 256>>>(out);
}